// round 2
// baseline (speedup 1.0000x reference)
#include <cuda_runtime.h>
#include <math.h>

#define Bb 2
#define Hh 16
#define Ss 2048
#define Dd 64
#define TQ 16
#define TPB 512
#define INV_TEMP 0.125f
#define NEGINF -1e9f

// Dynamic smem layout:
//   sq : TQ*Dd floats   (q tile)
//   sc : TQ*Ss floats   (score strip -> probs -> attn; reused as PV partials)
#define SMEM_FLOATS (TQ*Dd + TQ*Ss)

__global__ void __launch_bounds__(TPB, 1)
attn_kernel(const float* __restrict__ Q, const float* __restrict__ K,
            const float* __restrict__ V, const float* __restrict__ SENT,
            const int* __restrict__ MASK,
            float* __restrict__ OUT, float* __restrict__ ATTN)
{
    extern __shared__ float smem[];
    float* sq = smem;             // [TQ][Dd]
    float* sc = smem + TQ * Dd;   // [TQ][Ss]

    const int tid = threadIdx.x;
    const int q0  = blockIdx.x * TQ;
    const int h   = blockIdx.y;
    const int b   = blockIdx.z;
    const size_t head_off = ((size_t)(b * Hh + h)) * (size_t)Ss;

    // ---- load q tile ----
    {
        const float* qbase = Q + (head_off + (size_t)q0) * Dd;
        #pragma unroll
        for (int i = tid; i < TQ * Dd; i += TPB) sq[i] = qbase[i];
    }
    __syncthreads();

    const float4* k4base = (const float4*)(K + head_off * Dd);
    const float4* sq4    = (const float4*)sq;
    const int*    mrow   = MASK + b * Ss;

    // ---- Phase 1: scores (each thread owns one key column j, all TQ rows) ----
    for (int j = tid; j < Ss; j += TPB) {
        if (mrow[j] != 0) {
            float acc[TQ];
            #pragma unroll
            for (int r = 0; r < TQ; r++) acc[r] = 0.0f;
            const float4* krow = k4base + (size_t)j * (Dd / 4);
            #pragma unroll
            for (int c = 0; c < Dd / 4; c++) {
                float4 kv = krow[c];
                #pragma unroll
                for (int r = 0; r < TQ; r++) {
                    float4 qv = sq4[r * (Dd / 4) + c];
                    acc[r] = fmaf(qv.x, kv.x, acc[r]);
                    acc[r] = fmaf(qv.y, kv.y, acc[r]);
                    acc[r] = fmaf(qv.z, kv.z, acc[r]);
                    acc[r] = fmaf(qv.w, kv.w, acc[r]);
                }
            }
            #pragma unroll
            for (int r = 0; r < TQ; r++) sc[r * Ss + j] = acc[r] * INV_TEMP;
        } else {
            #pragma unroll
            for (int r = 0; r < TQ; r++) sc[r * Ss + j] = NEGINF;
        }
    }
    __syncthreads();

    // ---- Phase 2: fused softmax * sent_att, renormalize, write attn ----
    // Reference: softmax(s) * sent / sum(softmax(s)*sent)
    //          == exp(s-m)*sent / sum(exp(s-m)*sent)   (Z cancels)
    {
        const int wid = tid >> 5, lane = tid & 31;
        const int r = wid;                // 16 warps == 16 rows
        float* row = sc + r * Ss;
        float m = -INFINITY;
        for (int j = lane; j < Ss; j += 32) m = fmaxf(m, row[j]);
        #pragma unroll
        for (int o = 16; o > 0; o >>= 1) m = fmaxf(m, __shfl_xor_sync(0xFFFFFFFFu, m, o));

        const float* srow = SENT + b * Ss;
        float sum = 0.0f;
        for (int j = lane; j < Ss; j += 32) {
            float p = __expf(row[j] - m) * srow[j];
            row[j] = p;
            sum += p;
        }
        #pragma unroll
        for (int o = 16; o > 0; o >>= 1) sum += __shfl_xor_sync(0xFFFFFFFFu, sum, o);
        float inv = 1.0f / sum;

        float* arow = ATTN + (head_off + (size_t)(q0 + r)) * (size_t)Ss;
        for (int j = lane; j < Ss; j += 32) {
            float a = row[j] * inv;
            row[j] = a;
            arow[j] = a;
        }
    }
    __syncthreads();

    // ---- Phase 3: out = attn @ V ----
    // thread -> (d4 = tid & 15 : float4 chunk of D, jg = tid >> 4 : key-stripe 0..31)
    {
        const int d4 = tid & 15;
        const int jg = tid >> 4;
        const float4* v4base = (const float4*)(V + head_off * Dd);
        float4 acc4[TQ];
        #pragma unroll
        for (int r = 0; r < TQ; r++) acc4[r] = make_float4(0.f, 0.f, 0.f, 0.f);

        for (int j = jg; j < Ss; j += 32) {
            float4 vv = v4base[(size_t)j * (Dd / 4) + d4];
            #pragma unroll
            for (int r = 0; r < TQ; r++) {
                float a = sc[r * Ss + j];
                acc4[r].x = fmaf(a, vv.x, acc4[r].x);
                acc4[r].y = fmaf(a, vv.y, acc4[r].y);
                acc4[r].z = fmaf(a, vv.z, acc4[r].z);
                acc4[r].w = fmaf(a, vv.w, acc4[r].w);
            }
        }
        __syncthreads();   // all reads of sc complete -> safe to reuse as partials

        // partials: [jg][r][d4] float4  (32*16*16 float4 = 128KB, fits in sc)
        float4* part = (float4*)sc;
        #pragma unroll
        for (int r = 0; r < TQ; r++) part[(jg * TQ + r) * 16 + d4] = acc4[r];
        __syncthreads();

        if (tid < TQ * 16) {
            int r = tid >> 4, dd = tid & 15;
            float4 s = make_float4(0.f, 0.f, 0.f, 0.f);
            #pragma unroll
            for (int g = 0; g < 32; g++) {
                float4 p = part[(g * TQ + r) * 16 + dd];
                s.x += p.x; s.y += p.y; s.z += p.z; s.w += p.w;
            }
            float4* orow = (float4*)(OUT + (head_off + (size_t)(q0 + r)) * Dd);
            orow[dd] = s;
        }
    }
}

extern "C" void kernel_launch(void* const* d_in, const int* in_sizes, int n_in,
                              void* d_out, int out_size)
{
    const float* q    = (const float*)d_in[0];
    const float* k    = (const float*)d_in[1];
    const float* v    = (const float*)d_in[2];
    const float* sent = (const float*)d_in[3];
    const int*   mask = (const int*)d_in[4];

    float* out  = (float*)d_out;                              // [B,H,S,D]
    float* attn = out + (size_t)Bb * Hh * Ss * Dd;            // [B,H,S,S]

    size_t smem_bytes = (size_t)SMEM_FLOATS * sizeof(float);  // 135168 B
    cudaFuncSetAttribute(attn_kernel,
                         cudaFuncAttributeMaxDynamicSharedMemorySize,
                         (int)smem_bytes);

    dim3 grid(Ss / TQ, Hh, Bb);
    attn_kernel<<<grid, TPB, smem_bytes>>>(q, k, v, sent, mask, out, attn);
}